// round 2
// baseline (speedup 1.0000x reference)
#include <cuda_runtime.h>

// Problem constants
// P=4, B=2, S=2048, D=2048, H=16, HK=4, DH=128, G=4
// M (GEMM rows) = P*B*S = 16384

#define M_ROWS 16384

// -------- scratch (device globals: allocation-free) --------
__device__ float g_q[(size_t)M_ROWS * 2048];
__device__ float g_k[(size_t)M_ROWS * 512];
__device__ float g_v[(size_t)M_ROWS * 512];
__device__ float g_ctx[(size_t)M_ROWS * 2048];

// -------- helpers --------
__device__ __forceinline__ unsigned f2tf32(float f) {
    unsigned u;
    asm("cvt.rna.tf32.f32 %0, %1;" : "=r"(u) : "f"(f));
    return u;
}

__device__ __forceinline__ void mma_tf32(float* c, const unsigned* a, const unsigned* b) {
    asm volatile(
        "mma.sync.aligned.m16n8k8.row.col.f32.tf32.tf32.f32 "
        "{%0,%1,%2,%3}, {%4,%5,%6,%7}, {%8,%9}, {%0,%1,%2,%3};\n"
        : "+f"(c[0]), "+f"(c[1]), "+f"(c[2]), "+f"(c[3])
        : "r"(a[0]), "r"(a[1]), "r"(a[2]), "r"(a[3]), "r"(b[0]), "r"(b[1]));
}

// -------- TF32 GEMM: C[M,N] = A[M,K] @ W[K,N] (+ bias) --------
#define BM 128
#define BN 128
#define BKT 16
#define ASTR 24
#define BSTR 132

__device__ __forceinline__ void stage_store(
    unsigned* as, unsigned* bs, int ar, int ac, int br, int bc,
    float4 a0r, float4 a1r, float4 b0r, float4 b1r)
{
    as[ar * ASTR + ac + 0] = f2tf32(a0r.x);
    as[ar * ASTR + ac + 1] = f2tf32(a0r.y);
    as[ar * ASTR + ac + 2] = f2tf32(a0r.z);
    as[ar * ASTR + ac + 3] = f2tf32(a0r.w);
    as[(ar + 64) * ASTR + ac + 0] = f2tf32(a1r.x);
    as[(ar + 64) * ASTR + ac + 1] = f2tf32(a1r.y);
    as[(ar + 64) * ASTR + ac + 2] = f2tf32(a1r.z);
    as[(ar + 64) * ASTR + ac + 3] = f2tf32(a1r.w);
    bs[br * BSTR + bc + 0] = f2tf32(b0r.x);
    bs[br * BSTR + bc + 1] = f2tf32(b0r.y);
    bs[br * BSTR + bc + 2] = f2tf32(b0r.z);
    bs[br * BSTR + bc + 3] = f2tf32(b0r.w);
    bs[(br + 8) * BSTR + bc + 0] = f2tf32(b1r.x);
    bs[(br + 8) * BSTR + bc + 1] = f2tf32(b1r.y);
    bs[(br + 8) * BSTR + bc + 2] = f2tf32(b1r.z);
    bs[(br + 8) * BSTR + bc + 3] = f2tf32(b1r.w);
}

__device__ __forceinline__ void tile_compute(
    const unsigned* __restrict__ as, const unsigned* __restrict__ bs,
    int wm, int wn, int g, int tg, float acc[4][4][4])
{
#pragma unroll
    for (int kk = 0; kk < BKT; kk += 8) {
        unsigned af[4][4], bf[4][2];
#pragma unroll
        for (int mt = 0; mt < 4; mt++) {
            int r = wm * 64 + mt * 16 + g;
            af[mt][0] = as[r * ASTR + kk + tg];
            af[mt][1] = as[(r + 8) * ASTR + kk + tg];
            af[mt][2] = as[r * ASTR + kk + tg + 4];
            af[mt][3] = as[(r + 8) * ASTR + kk + tg + 4];
        }
#pragma unroll
        for (int nt = 0; nt < 4; nt++) {
            int cc = wn * 32 + nt * 8 + g;
            bf[nt][0] = bs[(kk + tg) * BSTR + cc];
            bf[nt][1] = bs[(kk + tg + 4) * BSTR + cc];
        }
#pragma unroll
        for (int mt = 0; mt < 4; mt++)
#pragma unroll
            for (int nt = 0; nt < 4; nt++)
                mma_tf32(acc[mt][nt], af[mt], bf[nt]);
    }
}

__global__ void __launch_bounds__(256, 2)
gemm_tf32(const float* __restrict__ A, const float* __restrict__ W,
          const float* __restrict__ bias, float* __restrict__ C,
          int N, int K)
{
    __shared__ unsigned As[2][BM * ASTR];
    __shared__ unsigned Bs[2][BKT * BSTR];

    const int t = threadIdx.x;
    const int lane = t & 31, warp = t >> 5;
    const int wm = warp >> 2, wn = warp & 3;
    const int g = lane >> 2, tg = lane & 3;
    const int bm = blockIdx.y * BM, bn = blockIdx.x * BN;

    const int ar = t >> 2;           // 0..63  (A rows ar, ar+64)
    const int ac = (t & 3) * 4;      // 0,4,8,12
    const int br = t >> 5;           // 0..7   (B rows br, br+8)
    const int bc = (t & 31) * 4;     // 0..124

    const float* Ag = A + (size_t)(bm + ar) * K + ac;
    const float* Wg = W + (size_t)br * N + bn + bc;
    const size_t wstep8 = (size_t)8 * N;

    float acc[4][4][4];
#pragma unroll
    for (int i = 0; i < 4; i++)
#pragma unroll
        for (int j = 0; j < 4; j++)
#pragma unroll
            for (int l = 0; l < 4; l++) acc[i][j][l] = 0.f;

    const int NT = K / BKT;

    float4 a0r, a1r, b0r, b1r;
    // prologue: tile 0
    a0r = *(const float4*)(Ag);
    a1r = *(const float4*)(Ag + (size_t)64 * K);
    b0r = *(const float4*)(Wg);
    b1r = *(const float4*)(Wg + wstep8);
    stage_store(As[0], Bs[0], ar, ac, br, bc, a0r, a1r, b0r, b1r);
    __syncthreads();

    for (int kt = 0; kt < NT; ++kt) {
        const int buf = kt & 1;
        if (kt + 1 < NT) {
            const float* Ap = Ag + (kt + 1) * BKT;
            a0r = *(const float4*)(Ap);
            a1r = *(const float4*)(Ap + (size_t)64 * K);
            const float* Wp = Wg + (size_t)(kt + 1) * BKT * N;
            b0r = *(const float4*)(Wp);
            b1r = *(const float4*)(Wp + wstep8);
        }
        tile_compute(As[buf], Bs[buf], wm, wn, g, tg, acc);
        __syncthreads();
        if (kt + 1 < NT) {
            stage_store(As[buf ^ 1], Bs[buf ^ 1], ar, ac, br, bc, a0r, a1r, b0r, b1r);
            __syncthreads();
        }
    }

    // epilogue
#pragma unroll
    for (int mt = 0; mt < 4; mt++) {
        const int r0 = bm + wm * 64 + mt * 16 + g;
#pragma unroll
        for (int nt = 0; nt < 4; nt++) {
            const int c0 = bn + wn * 32 + nt * 8 + tg * 2;
            float bb0 = bias ? bias[c0] : 0.f;
            float bb1 = bias ? bias[c0 + 1] : 0.f;
            float2 v0 = make_float2(acc[mt][nt][0] + bb0, acc[mt][nt][1] + bb1);
            float2 v1 = make_float2(acc[mt][nt][2] + bb0, acc[mt][nt][3] + bb1);
            *(float2*)(C + (size_t)r0 * N + c0) = v0;
            *(float2*)(C + (size_t)(r0 + 8) * N + c0) = v1;
        }
    }
}

// -------- attention over the replica axis (P=4) --------
// grid: (S=2048, B=2), block: 128 threads (warp w == q-replica p)
__global__ void __launch_bounds__(128)
attn_kernel(const float* __restrict__ Q, const float* __restrict__ K,
            const float* __restrict__ V, const float* __restrict__ cosp,
            const float* __restrict__ sinp, float* __restrict__ ctx)
{
    const int s = blockIdx.x;
    const int b = blockIdx.y;
    const int t = threadIdx.x;
    const int lane = t & 31;
    const int w = t >> 5;  // q replica p

    __shared__ float ksm[2048];  // [p][hk][d] : p*512 + hk*128 + d
    __shared__ float vsm[2048];
    __shared__ float cs[512];    // [p][d]
    __shared__ float sn[512];

    // cos/sin for this b
#pragma unroll
    for (int i = t; i < 512; i += 128) {
        cs[i] = cosp[b * 512 + i];
        sn[i] = sinp[b * 512 + i];
    }

    // load K,V: 2048 floats each, coalesced (512-wide rows)
#pragma unroll
    for (int j = 0; j < 16; ++j) {
        int i = j * 128 + t;
        int p = i >> 9;           // replica of kv row
        int col = i & 511;        // hk*128 + d
        size_t row = (size_t)(p * 2 + b) * 2048 + s;
        ksm[i] = K[row * 512 + col];
        vsm[i] = V[row * 512 + col];
    }
    __syncthreads();

    // RoPE K in shared (d == t since 128 threads; partner d^64)
    float kn[16];
#pragma unroll
    for (int j = 0; j < 16; ++j) {
        int i = j * 128 + t;
        int p = j >> 2;
        float c = cs[p * 128 + t];
        float sv = sn[p * 128 + t];
        float a = ksm[i];
        float pr = ksm[i ^ 64];
        kn[j] = a * c + ((t & 64) ? pr : -pr) * sv;
    }
    __syncthreads();
#pragma unroll
    for (int j = 0; j < 16; ++j) ksm[j * 128 + t] = kn[j];
    __syncthreads();

    const size_t qrow = (size_t)(w * 2 + b) * 2048 + s;
    const float c0 = cs[w * 128 + lane],      c1 = cs[w * 128 + lane + 32];
    const float c2 = cs[w * 128 + lane + 64], c3 = cs[w * 128 + lane + 96];
    const float s0 = sn[w * 128 + lane],      s1 = sn[w * 128 + lane + 32];
    const float s2 = sn[w * 128 + lane + 64], s3 = sn[w * 128 + lane + 96];

    for (int h = 0; h < 16; ++h) {
        const int hk = h & 3;
        const float* qp = Q + qrow * 2048 + h * 128;
        float q0 = qp[lane], q1 = qp[lane + 32], q2 = qp[lane + 64], q3 = qp[lane + 96];
        // RoPE Q (pairs d and d+64 both live in this lane)
        float qr0 = q0 * c0 - q2 * s0;
        float qr1 = q1 * c1 - q3 * s1;
        float qr2 = q2 * c2 + q0 * s2;
        float qr3 = q3 * c3 + q1 * s3;

        float sc[4];
#pragma unroll
        for (int qq = 0; qq < 4; ++qq) {
            const float* kp = ksm + qq * 512 + hk * 128;
            float part = qr0 * kp[lane] + qr1 * kp[lane + 32] +
                         qr2 * kp[lane + 64] + qr3 * kp[lane + 96];
#pragma unroll
            for (int o = 16; o; o >>= 1)
                part += __shfl_xor_sync(0xffffffffu, part, o);
            sc[qq] = part * 0.088388347648318447f;  // 1/sqrt(128)
        }
        // softmax over the 4 replicas
        float mx = fmaxf(fmaxf(sc[0], sc[1]), fmaxf(sc[2], sc[3]));
        float e0 = __expf(sc[0] - mx), e1 = __expf(sc[1] - mx);
        float e2 = __expf(sc[2] - mx), e3 = __expf(sc[3] - mx);
        float inv = 1.f / (e0 + e1 + e2 + e3);
        float a0 = e0 * inv, a1 = e1 * inv, a2 = e2 * inv, a3 = e3 * inv;

        float o0 = 0.f, o1 = 0.f, o2 = 0.f, o3 = 0.f;
        const float* v0p = vsm + 0 * 512 + hk * 128;
        const float* v1p = vsm + 1 * 512 + hk * 128;
        const float* v2p = vsm + 2 * 512 + hk * 128;
        const float* v3p = vsm + 3 * 512 + hk * 128;
        o0 = a0 * v0p[lane]      + a1 * v1p[lane]      + a2 * v2p[lane]      + a3 * v3p[lane];
        o1 = a0 * v0p[lane + 32] + a1 * v1p[lane + 32] + a2 * v2p[lane + 32] + a3 * v3p[lane + 32];
        o2 = a0 * v0p[lane + 64] + a1 * v1p[lane + 64] + a2 * v2p[lane + 64] + a3 * v3p[lane + 64];
        o3 = a0 * v0p[lane + 96] + a1 * v1p[lane + 96] + a2 * v2p[lane + 96] + a3 * v3p[lane + 96];

        float* op = ctx + qrow * 2048 + h * 128;
        op[lane] = o0; op[lane + 32] = o1; op[lane + 64] = o2; op[lane + 96] = o3;
    }
}

// -------- launch --------
extern "C" void kernel_launch(void* const* d_in, const int* in_sizes, int n_in,
                              void* d_out, int out_size)
{
    const float* hs   = (const float*)d_in[0];
    const float* cosp = (const float*)d_in[1];
    const float* sinp = (const float*)d_in[2];
    const float* Wq   = (const float*)d_in[3];
    const float* bq   = (const float*)d_in[4];
    const float* Wk   = (const float*)d_in[5];
    const float* bk   = (const float*)d_in[6];
    const float* Wv   = (const float*)d_in[7];
    const float* bv   = (const float*)d_in[8];
    const float* Wo   = (const float*)d_in[9];
    float* out = (float*)d_out;

    void *pq, *pk, *pv, *pc;
    cudaGetSymbolAddress(&pq, g_q);
    cudaGetSymbolAddress(&pk, g_k);
    cudaGetSymbolAddress(&pv, g_v);
    cudaGetSymbolAddress(&pc, g_ctx);

    dim3 blk(256);
    // Q projection: N=2048
    gemm_tf32<<<dim3(2048 / BN, M_ROWS / BM), blk>>>(hs, Wq, bq, (float*)pq, 2048, 2048);
    // K projection: N=512
    gemm_tf32<<<dim3(512 / BN, M_ROWS / BM), blk>>>(hs, Wk, bk, (float*)pk, 512, 2048);
    // V projection: N=512
    gemm_tf32<<<dim3(512 / BN, M_ROWS / BM), blk>>>(hs, Wv, bv, (float*)pv, 512, 2048);
    // replica attention
    attn_kernel<<<dim3(2048, 2), 128>>>((const float*)pq, (const float*)pk, (const float*)pv,
                                        cosp, sinp, (float*)pc);
    // output projection
    gemm_tf32<<<dim3(2048 / BN, M_ROWS / BM), blk>>>((const float*)pc, Wo, nullptr, out, 2048, 2048);
}

// round 4
// speedup vs baseline: 2.6187x; 2.6187x over previous
#include <cuda_runtime.h>
#include <cuda_fp16.h>
#include <cstdint>

// Problem: P=4, B=2, S=2048, D=2048, H=16, HK=4, DH=128, G=4
#define M_ROWS 16384
#define KD     2048

// -------- scratch (device globals: allocation-free) --------
__device__ __half g_hs_h[(size_t)M_ROWS * KD];
__device__ __half g_wq_h[(size_t)KD * 2048];
__device__ __half g_wk_h[(size_t)KD * 512];
__device__ __half g_wv_h[(size_t)KD * 512];
__device__ __half g_wo_h[(size_t)2048 * 2048];
__device__ __half g_ctx_h[(size_t)M_ROWS * 2048];
__device__ float  g_q[(size_t)M_ROWS * 2048];
__device__ float  g_k[(size_t)M_ROWS * 512];
__device__ float  g_v[(size_t)M_ROWS * 512];

// -------- GEMM config --------
#define BM 128
#define BN 128
#define BK 32                  // halves per k-stage
#define NTILE (KD / BK)        // 64
#define STAGES 3
#define ASTR 40                // halves per A smem row (80B: odd multiple of 16B)
#define BSTR 136               // halves per B smem row (272B: odd multiple of 16B)
#define A_STAGE (BM * ASTR)    // 5120 halves
#define B_STAGE (BK * BSTR)    // 4352 halves
#define SMEM_HALVES (STAGES * (A_STAGE + B_STAGE))
#define SMEM_BYTES  (SMEM_HALVES * 2)   // 56832

// -------- PTX helpers --------
__device__ __forceinline__ uint32_t s2u(const void* p) {
    uint32_t a;
    asm("{ .reg .u64 t; cvta.to.shared.u64 t, %1; cvt.u32.u64 %0, t; }" : "=r"(a) : "l"(p));
    return a;
}
__device__ __forceinline__ void cp16(uint32_t dst, const void* src) {
    asm volatile("cp.async.cg.shared.global [%0], [%1], 16;" :: "r"(dst), "l"(src));
}
__device__ __forceinline__ void cp_commit() {
    asm volatile("cp.async.commit_group;" ::: "memory");
}
__device__ __forceinline__ void ldsm4(uint32_t* r, uint32_t addr) {
    asm volatile("ldmatrix.sync.aligned.m8n8.x4.shared.b16 {%0,%1,%2,%3}, [%4];"
        : "=r"(r[0]), "=r"(r[1]), "=r"(r[2]), "=r"(r[3]) : "r"(addr));
}
__device__ __forceinline__ void ldsm4t(uint32_t* r, uint32_t addr) {
    asm volatile("ldmatrix.sync.aligned.m8n8.x4.trans.shared.b16 {%0,%1,%2,%3}, [%4];"
        : "=r"(r[0]), "=r"(r[1]), "=r"(r[2]), "=r"(r[3]) : "r"(addr));
}
__device__ __forceinline__ void mma_h(float* c, const uint32_t* a, const uint32_t* b) {
    asm volatile(
        "mma.sync.aligned.m16n8k16.row.col.f32.f16.f16.f32 "
        "{%0,%1,%2,%3}, {%4,%5,%6,%7}, {%8,%9}, {%0,%1,%2,%3};"
        : "+f"(c[0]), "+f"(c[1]), "+f"(c[2]), "+f"(c[3])
        : "r"(a[0]), "r"(a[1]), "r"(a[2]), "r"(a[3]), "r"(b[0]), "r"(b[1]));
}

// -------- fp16 tensor-core GEMM: C[M,N](f32) = A[M,K](f16) @ B[K,N](f16) (+bias) --------
__global__ void __launch_bounds__(256, 2)
gemm_h(const __half* __restrict__ A, const __half* __restrict__ B,
       const float* __restrict__ bias, float* __restrict__ C, int N)
{
    extern __shared__ __half sm[];
    __half* sA = sm;
    __half* sB = sm + STAGES * A_STAGE;

    const int t = threadIdx.x, lane = t & 31, warp = t >> 5;
    const int wm = warp >> 2, wn = warp & 3;      // 2 x 4 warp grid, warp tile 64x32
    const int g = lane >> 2, tg = lane & 3;
    const int bm = blockIdx.y * BM, bn = blockIdx.x * BN;

    // cp.async staging map
    const int ar = t >> 1;              // A row 0..127
    const int ac = (t & 1) * 16;        // halves 0 or 16 (two 16B chunks each)
    const int br = t >> 3;              // B row 0..31
    const int bc = (t & 7) * 16;        // halves 0..112

    const __half* Ag = A + (size_t)(bm + ar) * KD + ac;
    const __half* Bg = B + (size_t)br * N + bn + bc;

    // ldmatrix lane addressing (precomputed halves offsets)
    const int a_row = (lane & 15);                 // within 16-row frag
    const int a_col = ((lane >> 4) << 3);          // 0 or 8
    const int b_row = (lane & 7) + (((lane >> 3) & 1) << 3);  // 0..15
    const int b_col = ((lane >> 4) << 3);          // 0 or 8

    float acc[4][4][4];
#pragma unroll
    for (int i = 0; i < 4; i++)
#pragma unroll
        for (int j = 0; j < 4; j++)
#pragma unroll
            for (int l = 0; l < 4; l++) acc[i][j][l] = 0.f;

    // prologue: issue STAGES-1 stages
#pragma unroll
    for (int s = 0; s < STAGES - 1; s++) {
        uint32_t da = s2u(sA + s * A_STAGE + ar * ASTR + ac);
        const __half* Ap = Ag + s * BK;
        cp16(da, Ap); cp16(da + 16, Ap + 8);
        uint32_t db = s2u(sB + s * B_STAGE + br * BSTR + bc);
        const __half* Bp = Bg + (size_t)s * BK * N;
        cp16(db, Bp); cp16(db + 16, Bp + 8);
        cp_commit();
    }

    for (int kt = 0; kt < NTILE; kt++) {
        const int s = kt % STAGES;
        asm volatile("cp.async.wait_group %0;" :: "n"(STAGES - 2));
        __syncthreads();

        // issue the next stage (slot consumed at kt-1; all threads past sync)
        if (kt + STAGES - 1 < NTILE) {
            const int sn = (kt + STAGES - 1) % STAGES;
            uint32_t da = s2u(sA + sn * A_STAGE + ar * ASTR + ac);
            const __half* Ap = Ag + (kt + STAGES - 1) * BK;
            cp16(da, Ap); cp16(da + 16, Ap + 8);
            uint32_t db = s2u(sB + sn * B_STAGE + br * BSTR + bc);
            const __half* Bp = Bg + (size_t)(kt + STAGES - 1) * BK * N;
            cp16(db, Bp); cp16(db + 16, Bp + 8);
            cp_commit();
        }

        // compute this stage: 2 k16 sub-steps
        const __half* a0 = sA + s * A_STAGE;
        const __half* b0 = sB + s * B_STAGE;
#pragma unroll
        for (int kk = 0; kk < 2; kk++) {
            uint32_t af[4][4];
#pragma unroll
            for (int mt = 0; mt < 4; mt++) {
                int row = wm * 64 + mt * 16 + a_row;
                ldsm4(af[mt], s2u(a0 + row * ASTR + kk * 16 + a_col));
            }
            uint32_t bf[4][2];
#pragma unroll
            for (int nt2 = 0; nt2 < 2; nt2++) {
                uint32_t rr[4];
                int row = kk * 16 + b_row;
                int col = wn * 32 + nt2 * 16 + b_col;
                ldsm4t(rr, s2u(b0 + row * BSTR + col));
                bf[nt2 * 2][0] = rr[0]; bf[nt2 * 2][1] = rr[1];
                bf[nt2 * 2 + 1][0] = rr[2]; bf[nt2 * 2 + 1][1] = rr[3];
            }
#pragma unroll
            for (int mt = 0; mt < 4; mt++)
#pragma unroll
                for (int nt = 0; nt < 4; nt++)
                    mma_h(acc[mt][nt], af[mt], bf[nt]);
        }
    }

    // epilogue
#pragma unroll
    for (int mt = 0; mt < 4; mt++) {
        const int r0 = bm + wm * 64 + mt * 16 + g;
#pragma unroll
        for (int nt = 0; nt < 4; nt++) {
            const int c0 = bn + wn * 32 + nt * 8 + tg * 2;
            float bb0 = bias ? bias[c0] : 0.f;
            float bb1 = bias ? bias[c0 + 1] : 0.f;
            float2 v0 = make_float2(acc[mt][nt][0] + bb0, acc[mt][nt][1] + bb1);
            float2 v1 = make_float2(acc[mt][nt][2] + bb0, acc[mt][nt][3] + bb1);
            *(float2*)(C + (size_t)r0 * N + c0) = v0;
            *(float2*)(C + (size_t)(r0 + 8) * N + c0) = v1;
        }
    }
}

// -------- fp32 -> fp16 conversion --------
__global__ void f2h_kernel(const float4* __restrict__ in, uint2* __restrict__ out, int n4)
{
    int i = blockIdx.x * blockDim.x + threadIdx.x;
    const int stride = gridDim.x * blockDim.x;
    for (; i < n4; i += stride) {
        float4 v = in[i];
        __half2 lo = __floats2half2_rn(v.x, v.y);
        __half2 hi = __floats2half2_rn(v.z, v.w);
        uint2 o;
        o.x = *reinterpret_cast<uint32_t*>(&lo);
        o.y = *reinterpret_cast<uint32_t*>(&hi);
        out[i] = o;
    }
}

// -------- attention over the replica axis (P=4) --------
__global__ void __launch_bounds__(128)
attn_kernel(const float* __restrict__ Q, const float* __restrict__ K,
            const float* __restrict__ V, const float* __restrict__ cosp,
            const float* __restrict__ sinp, __half* __restrict__ ctx)
{
    const int s = blockIdx.x;
    const int b = blockIdx.y;
    const int t = threadIdx.x;
    const int lane = t & 31;
    const int w = t >> 5;  // q replica p

    __shared__ float ksm[2048];  // [p][hk][d]
    __shared__ float vsm[2048];
    __shared__ float cs[512];
    __shared__ float sn[512];

#pragma unroll
    for (int i = t; i < 512; i += 128) {
        cs[i] = cosp[b * 512 + i];
        sn[i] = sinp[b * 512 + i];
    }
#pragma unroll
    for (int j = 0; j < 16; ++j) {
        int i = j * 128 + t;
        int p = i >> 9;
        int col = i & 511;
        size_t row = (size_t)(p * 2 + b) * 2048 + s;
        ksm[i] = K[row * 512 + col];
        vsm[i] = V[row * 512 + col];
    }
    __syncthreads();

    float kn[16];
#pragma unroll
    for (int j = 0; j < 16; ++j) {
        int i = j * 128 + t;
        int p = j >> 2;
        float c = cs[p * 128 + t];
        float sv = sn[p * 128 + t];
        float a = ksm[i];
        float pr = ksm[i ^ 64];
        kn[j] = a * c + ((t & 64) ? pr : -pr) * sv;
    }
    __syncthreads();
#pragma unroll
    for (int j = 0; j < 16; ++j) ksm[j * 128 + t] = kn[j];
    __syncthreads();

    const size_t qrow = (size_t)(w * 2 + b) * 2048 + s;
    const float c0 = cs[w * 128 + lane],      c1 = cs[w * 128 + lane + 32];
    const float c2 = cs[w * 128 + lane + 64], c3 = cs[w * 128 + lane + 96];
    const float s0 = sn[w * 128 + lane],      s1 = sn[w * 128 + lane + 32];
    const float s2 = sn[w * 128 + lane + 64], s3 = sn[w * 128 + lane + 96];

    for (int h = 0; h < 16; ++h) {
        const int hk = h & 3;
        const float* qp = Q + qrow * 2048 + h * 128;
        float q0 = qp[lane], q1 = qp[lane + 32], q2 = qp[lane + 64], q3 = qp[lane + 96];
        float qr0 = q0 * c0 - q2 * s0;
        float qr1 = q1 * c1 - q3 * s1;
        float qr2 = q2 * c2 + q0 * s2;
        float qr3 = q3 * c3 + q1 * s3;

        float sc[4];
#pragma unroll
        for (int qq = 0; qq < 4; ++qq) {
            const float* kp = ksm + qq * 512 + hk * 128;
            float part = qr0 * kp[lane] + qr1 * kp[lane + 32] +
                         qr2 * kp[lane + 64] + qr3 * kp[lane + 96];
#pragma unroll
            for (int o = 16; o; o >>= 1)
                part += __shfl_xor_sync(0xffffffffu, part, o);
            sc[qq] = part * 0.088388347648318447f;  // 1/sqrt(128)
        }
        float mx = fmaxf(fmaxf(sc[0], sc[1]), fmaxf(sc[2], sc[3]));
        float e0 = __expf(sc[0] - mx), e1 = __expf(sc[1] - mx);
        float e2 = __expf(sc[2] - mx), e3 = __expf(sc[3] - mx);
        float inv = 1.f / (e0 + e1 + e2 + e3);
        float a0 = e0 * inv, a1 = e1 * inv, a2 = e2 * inv, a3 = e3 * inv;

        const float* v0p = vsm + 0 * 512 + hk * 128;
        const float* v1p = vsm + 1 * 512 + hk * 128;
        const float* v2p = vsm + 2 * 512 + hk * 128;
        const float* v3p = vsm + 3 * 512 + hk * 128;
        float o0 = a0 * v0p[lane]      + a1 * v1p[lane]      + a2 * v2p[lane]      + a3 * v3p[lane];
        float o1 = a0 * v0p[lane + 32] + a1 * v1p[lane + 32] + a2 * v2p[lane + 32] + a3 * v3p[lane + 32];
        float o2 = a0 * v0p[lane + 64] + a1 * v1p[lane + 64] + a2 * v2p[lane + 64] + a3 * v3p[lane + 64];
        float o3 = a0 * v0p[lane + 96] + a1 * v1p[lane + 96] + a2 * v2p[lane + 96] + a3 * v3p[lane + 96];

        __half* op = ctx + qrow * 2048 + h * 128;
        op[lane]      = __float2half_rn(o0);
        op[lane + 32] = __float2half_rn(o1);
        op[lane + 64] = __float2half_rn(o2);
        op[lane + 96] = __float2half_rn(o3);
    }
}

// -------- launch --------
extern "C" void kernel_launch(void* const* d_in, const int* in_sizes, int n_in,
                              void* d_out, int out_size)
{
    const float* hs   = (const float*)d_in[0];
    const float* cosp = (const float*)d_in[1];
    const float* sinp = (const float*)d_in[2];
    const float* Wq   = (const float*)d_in[3];
    const float* bq   = (const float*)d_in[4];
    const float* Wk   = (const float*)d_in[5];
    const float* bk   = (const float*)d_in[6];
    const float* Wv   = (const float*)d_in[7];
    const float* bv   = (const float*)d_in[8];
    const float* Wo   = (const float*)d_in[9];
    float* out = (float*)d_out;

    void *phs, *pwq, *pwk, *pwv, *pwo, *pctx, *pq, *pk, *pv;
    cudaGetSymbolAddress(&phs, g_hs_h);
    cudaGetSymbolAddress(&pwq, g_wq_h);
    cudaGetSymbolAddress(&pwk, g_wk_h);
    cudaGetSymbolAddress(&pwv, g_wv_h);
    cudaGetSymbolAddress(&pwo, g_wo_h);
    cudaGetSymbolAddress(&pctx, g_ctx_h);
    cudaGetSymbolAddress(&pq, g_q);
    cudaGetSymbolAddress(&pk, g_k);
    cudaGetSymbolAddress(&pv, g_v);

    cudaFuncSetAttribute(gemm_h, cudaFuncAttributeMaxDynamicSharedMemorySize, SMEM_BYTES);

    // fp32 -> fp16 conversions
    f2h_kernel<<<2048, 256>>>((const float4*)hs, (uint2*)phs, (M_ROWS * KD) / 4);
    f2h_kernel<<<512, 256>>>((const float4*)Wq, (uint2*)pwq, (KD * 2048) / 4);
    f2h_kernel<<<256, 256>>>((const float4*)Wk, (uint2*)pwk, (KD * 512) / 4);
    f2h_kernel<<<256, 256>>>((const float4*)Wv, (uint2*)pwv, (KD * 512) / 4);
    f2h_kernel<<<512, 256>>>((const float4*)Wo, (uint2*)pwo, (2048 * 2048) / 4);

    // projections
    gemm_h<<<dim3(2048 / BN, M_ROWS / BM), 256, SMEM_BYTES>>>(
        (const __half*)phs, (const __half*)pwq, bq, (float*)pq, 2048);
    gemm_h<<<dim3(512 / BN, M_ROWS / BM), 256, SMEM_BYTES>>>(
        (const __half*)phs, (const __half*)pwk, bk, (float*)pk, 512);
    gemm_h<<<dim3(512 / BN, M_ROWS / BM), 256, SMEM_BYTES>>>(
        (const __half*)phs, (const __half*)pwv, bv, (float*)pv, 512);

    // replica attention (writes fp16 ctx)
    attn_kernel<<<dim3(2048, 2), 128>>>((const float*)pq, (const float*)pk, (const float*)pv,
                                        cosp, sinp, (__half*)pctx);

    // output projection
    gemm_h<<<dim3(2048 / BN, M_ROWS / BM), 256, SMEM_BYTES>>>(
        (const __half*)pctx, (const __half*)pwo, nullptr, out, 2048);
}